// round 3
// baseline (speedup 1.0000x reference)
#include <cuda_runtime.h>

// NavierStokesLossMAC: fused residual + masked MSE, single-kernel version.
// smem-tiled 128x8 stencil, per-block partials, counter-based finalization.

static constexpr int B = 8;
static constexpr int H = 1024;
static constexpr int W = 1024;
static constexpr float MU = 0.1f;
static constexpr float INV_DT = 0.25f;      // 1/DT, DT=4

static constexpr int TX = 8;                // x tiles (128 px each)
static constexpr int TY = 128;              // y tiles (8 rows each)
static constexpr int NPART = B * TY * TX;   // 8192
static constexpr int SW = 136;              // smem row width (4-px halo both sides)

__device__ float        g_part[NPART];
__device__ unsigned int g_count = 0;

__global__ __launch_bounds__(256) void ns_loss_kernel(
    const float* __restrict__ v_old,
    const float* __restrict__ v_new,
    const float* __restrict__ p_new,
    const int*   __restrict__ mask,
    float*       __restrict__ out)
{
    __shared__ float su[10][SW];   // u avg, rows gy0-1 .. gy0+8
    __shared__ float sw[10][SW];   // w avg
    __shared__ float sdu[8][SW];   // (u_new-u_old)/DT, center rows only
    __shared__ float sdw[8][SW];
    __shared__ float sp[9][SW];    // p, rows gy0-1 .. gy0+7

    const int bx = blockIdx.x;     // 0..7
    const int by = blockIdx.y;     // 0..127
    const int b  = blockIdx.z;     // 0..7
    const int tid = threadIdx.x;

    const size_t plane = (size_t)H * W;
    const float* uo = v_old + (size_t)b * 2 * plane;
    const float* wo = uo + plane;
    const float* un = v_new + (size_t)b * 2 * plane;
    const float* wn = un + plane;
    const float* pp = p_new + (size_t)b * plane;
    const int*   mm = mask  + (size_t)b * plane;

    const int gy0     = by * 8;          // first center row of tile
    const int gx_base = bx * 128 - 4;    // first loaded column (4-px halo)

    // ---- load phase: velocities (10 rows x 34 float4) ----
    for (int idx = tid; idx < 340; idx += 256) {
        const int r = idx / 34, c = idx - r * 34;
        const int gy = min(max(gy0 - 1 + r, 0), H - 1);
        const int gx = min(max(gx_base + c * 4, 0), W - 4);
        const size_t off = (size_t)gy * W + gx;

        float4 a = *(const float4*)(uo + off);
        float4 n = *(const float4*)(un + off);
        su[r][c*4+0] = 0.5f*(a.x+n.x); su[r][c*4+1] = 0.5f*(a.y+n.y);
        su[r][c*4+2] = 0.5f*(a.z+n.z); su[r][c*4+3] = 0.5f*(a.w+n.w);
        if (r >= 1 && r <= 8) {
            sdu[r-1][c*4+0] = (n.x-a.x)*INV_DT; sdu[r-1][c*4+1] = (n.y-a.y)*INV_DT;
            sdu[r-1][c*4+2] = (n.z-a.z)*INV_DT; sdu[r-1][c*4+3] = (n.w-a.w)*INV_DT;
        }
        a = *(const float4*)(wo + off);
        n = *(const float4*)(wn + off);
        sw[r][c*4+0] = 0.5f*(a.x+n.x); sw[r][c*4+1] = 0.5f*(a.y+n.y);
        sw[r][c*4+2] = 0.5f*(a.z+n.z); sw[r][c*4+3] = 0.5f*(a.w+n.w);
        if (r >= 1 && r <= 8) {
            sdw[r-1][c*4+0] = (n.x-a.x)*INV_DT; sdw[r-1][c*4+1] = (n.y-a.y)*INV_DT;
            sdw[r-1][c*4+2] = (n.z-a.z)*INV_DT; sdw[r-1][c*4+3] = (n.w-a.w)*INV_DT;
        }
    }
    // ---- pressure (9 rows x 34 float4) ----
    for (int idx = tid; idx < 306; idx += 256) {
        const int r = idx / 34, c = idx - r * 34;
        const int gy = min(max(gy0 - 1 + r, 0), H - 1);
        const int gx = min(max(gx_base + c * 4, 0), W - 4);
        float4 v = *(const float4*)(pp + (size_t)gy * W + gx);
        sp[r][c*4+0] = v.x; sp[r][c*4+1] = v.y; sp[r][c*4+2] = v.z; sp[r][c*4+3] = v.w;
    }
    __syncthreads();

    // ---- compute phase: 32x8 threads, each a 4-px quad ----
    const int tx = tid & 31, ty = tid >> 5;
    const int gy = gy0 + ty;             // global center row
    const int rc = ty + 1;               // smem halo-row index
    const int sc = 4 + tx * 4;           // smem col of quad start
    const int x0g = bx * 128 + tx * 4;   // global col of quad start

    float4 ucv  = *(const float4*)&su[rc][sc];
    float  u_l  = su[rc][sc-1], u_r = su[rc][sc+4];
    float4 wcv  = *(const float4*)&sw[rc][sc];
    float  w_l  = sw[rc][sc-1], w_r = sw[rc][sc+4];
    float4 uymv = *(const float4*)&su[rc-1][sc];
    float4 uypv = *(const float4*)&su[rc+1][sc];
    float4 wymv = *(const float4*)&sw[rc-1][sc];
    float4 wypv = *(const float4*)&sw[rc+1][sc];
    float4 duv  = *(const float4*)&sdu[ty][sc];
    float4 dwv  = *(const float4*)&sdw[ty][sc];
    float4 pcv  = *(const float4*)&sp[rc][sc];
    float  p_l  = sp[rc][sc-1];
    float4 pymv = *(const float4*)&sp[rc-1][sc];
    int4   mk   = *(const int4*)(mm + (size_t)gy * W + x0g);

    const float uc6[6] = {u_l, ucv.x, ucv.y, ucv.z, ucv.w, u_r};
    const float wc6[6] = {w_l, wcv.x, wcv.y, wcv.z, wcv.w, w_r};
    const float pc5[5] = {p_l, pcv.x, pcv.y, pcv.z, pcv.w};
    const float uym[4] = {uymv.x, uymv.y, uymv.z, uymv.w};
    const float uyp[4] = {uypv.x, uypv.y, uypv.z, uypv.w};
    const float wym[4] = {wymv.x, wymv.y, wymv.z, wymv.w};
    const float wyp[4] = {wypv.x, wypv.y, wypv.z, wypv.w};
    const float du4[4] = {duv.x, duv.y, duv.z, duv.w};
    const float dw4[4] = {dwv.x, dwv.y, dwv.z, dwv.w};
    const float pym[4] = {pymv.x, pymv.y, pymv.z, pymv.w};
    const int   mk4[4] = {mk.x, mk.y, mk.z, mk.w};

    float local = 0.0f;
    const bool row_ok = (gy >= 1) && (gy <= H - 2);
    #pragma unroll
    for (int j = 0; j < 4; ++j) {
        const float u_c  = uc6[j+1], u_xm = uc6[j], u_xp = uc6[j+2];
        const float w_c  = wc6[j+1], w_xm = wc6[j], w_xp = wc6[j+2];

        // res_x (RHO = 1)
        float rx = dw4[j]
                 + w_c * 0.5f * (w_xp - w_xm)
                 + 0.5f * ( 0.5f*(u_c + u_xm) * (w_c - wym[j])
                          + 0.5f*(u_c + u_xp) * (wyp[j] - w_c) )
                 + (pc5[j+1] - pc5[j])
                 - MU * (w_xm + w_xp + wym[j] + wyp[j] - 4.0f * w_c);

        // res_y
        float ry = du4[j]
                 + u_c * 0.5f * (uyp[j] - uym[j])
                 + 0.5f * ( 0.5f*(w_c + wym[j]) * (u_c - u_xm)
                          + 0.5f*(w_c + wyp[j]) * (u_xp - u_c) )
                 + (pc5[j+1] - pym[j])
                 - MU * (u_xm + u_xp + uym[j] + uyp[j] - 4.0f * u_c);

        const float mf = (float)mk4[j];
        rx *= mf;
        ry *= mf;

        const int x = x0g + j;
        if (row_ok && x >= 1 && x <= W - 2)
            local += rx * rx + ry * ry;
    }

    // ---- block reduction ----
    #pragma unroll
    for (int o = 16; o > 0; o >>= 1)
        local += __shfl_xor_sync(0xffffffffu, local, o);

    __shared__ float s_part[8];
    __shared__ bool  s_last;
    const int lane = tid & 31, wid = tid >> 5;
    if (lane == 0) s_part[wid] = local;
    __syncthreads();
    if (tid < 32) {
        float v = (tid < 8) ? s_part[tid] : 0.0f;
        #pragma unroll
        for (int o = 4; o > 0; o >>= 1)
            v += __shfl_xor_sync(0xffffffffu, v, o);
        if (tid == 0) {
            g_part[(b * TY + by) * TX + bx] = v;
            __threadfence();
            unsigned int old = atomicAdd(&g_count, 1u);
            s_last = (old == (unsigned)(NPART - 1));
        }
    }
    __syncthreads();

    // ---- last block finalizes: 8 warps, one per batch ----
    if (s_last) {
        __threadfence();
        const int wi = tid >> 5, l = tid & 31;   // warp wi handles batch wi
        double s = 0.0;
        #pragma unroll 4
        for (int k = l; k < TY * TX; k += 32)
            s += (double)g_part[wi * TY * TX + k];
        #pragma unroll
        for (int o = 16; o > 0; o >>= 1)
            s += __shfl_xor_sync(0xffffffffu, s, o);
        if (l == 0)
            out[wi] = (float)(s * (1.0 / ((double)(H - 2) * (double)(W - 2))));
        if (tid == 0) g_count = 0;               // reset for next graph replay
    }
}

extern "C" void kernel_launch(void* const* d_in, const int* in_sizes, int n_in,
                              void* d_out, int out_size) {
    const float* v_old = (const float*)d_in[0];
    const float* v_new = (const float*)d_in[1];
    const float* p_new = (const float*)d_in[2];
    const int*   mask  = (const int*)d_in[3];
    float* out = (float*)d_out;

    dim3 grid(TX, TY, B);            // 8 x 128 x 8 = 8192 blocks
    ns_loss_kernel<<<grid, 256>>>(v_old, v_new, p_new, mask, out);
}

// round 5
// speedup vs baseline: 1.1276x; 1.1276x over previous
#include <cuda_runtime.h>

// NavierStokesLossMAC: fused residual + masked MSE, single kernel.
// Direct-load stencil (L1 serves halo reuse), 2 output rows per thread to
// cut vertical L2 redundancy, counter-based single-kernel finalization.

static constexpr int B = 8;
static constexpr int H = 1024;
static constexpr int W = 1024;
static constexpr float MU = 0.1f;
static constexpr float INV_DT = 0.25f;   // 1/DT, DT=4

static constexpr int RPB   = 2;                  // output rows per block
static constexpr int TYB   = (H - 2) / RPB;      // 511 y-blocks
static constexpr int NPART = B * TYB;            // 4088 partials

__device__ float        g_part[NPART];
__device__ unsigned int g_count = 0;

__global__ __launch_bounds__(256) void ns_loss_kernel(
    const float* __restrict__ v_old,
    const float* __restrict__ v_new,
    const float* __restrict__ p_new,
    const int*   __restrict__ mask,
    float*       __restrict__ out)
{
    const int b   = blockIdx.z;
    const int y0  = 1 + blockIdx.y * RPB;   // center rows y0, y0+1 (1..1021)
    const int x0  = threadIdx.x * 4;
    const int tid = threadIdx.x;

    const size_t plane = (size_t)H * W;
    const float* uo = v_old + (size_t)b * 2 * plane;   // channel 0 = u
    const float* wo = uo + plane;                       // channel 1 = w
    const float* un = v_new + (size_t)b * 2 * plane;
    const float* wn = un + plane;
    const float* pp = p_new + (size_t)b * plane;
    const int*   mm = mask  + (size_t)b * plane;

    // row base offsets: rows y0-1 .. y0+2  (all in [0, H-1], no clamping)
    int roff[4];
    #pragma unroll
    for (int i = 0; i < 4; ++i) roff[i] = (y0 - 1 + i) * W + x0;

    // ---- issue all loads up front (independent -> max MLP) ----
    float4 uo4[4], un4[4], wo4[4], wn4[4];
    #pragma unroll
    for (int i = 0; i < 4; ++i) {
        uo4[i] = *(const float4*)(uo + roff[i]);
        un4[i] = *(const float4*)(un + roff[i]);
        wo4[i] = *(const float4*)(wo + roff[i]);
        wn4[i] = *(const float4*)(wn + roff[i]);
    }
    // x-halos only for the two center rows (indices 1,2); x0-1 / x0+4 stay
    // inside the plane for y0>=1 (edge garbage is excluded from the sum).
    float uoh[2][2], unh[2][2], woh[2][2], wnh[2][2];
    #pragma unroll
    for (int i = 0; i < 2; ++i) {
        const int rl = roff[i + 1] - 1, rr = roff[i + 1] + 4;
        uoh[i][0] = uo[rl]; uoh[i][1] = uo[rr];
        unh[i][0] = un[rl]; unh[i][1] = un[rr];
        woh[i][0] = wo[rl]; woh[i][1] = wo[rr];
        wnh[i][0] = wn[rl]; wnh[i][1] = wn[rr];
    }
    float4 p4[3];                 // p rows y0-1, y0, y0+1
    #pragma unroll
    for (int i = 0; i < 3; ++i) p4[i] = *(const float4*)(pp + roff[i]);
    float pl[2] = {pp[roff[1] - 1], pp[roff[2] - 1]};
    int4 mk[2]  = {*(const int4*)(mm + roff[1]), *(const int4*)(mm + roff[2])};

    // ---- combine: time-averaged velocities + dt terms ----
    float uA[4][4], wA[4][4];
    #pragma unroll
    for (int i = 0; i < 4; ++i) {
        uA[i][0] = 0.5f*(uo4[i].x+un4[i].x); uA[i][1] = 0.5f*(uo4[i].y+un4[i].y);
        uA[i][2] = 0.5f*(uo4[i].z+un4[i].z); uA[i][3] = 0.5f*(uo4[i].w+un4[i].w);
        wA[i][0] = 0.5f*(wo4[i].x+wn4[i].x); wA[i][1] = 0.5f*(wo4[i].y+wn4[i].y);
        wA[i][2] = 0.5f*(wo4[i].z+wn4[i].z); wA[i][3] = 0.5f*(wo4[i].w+wn4[i].w);
    }
    float du[2][4], dw[2][4], uH[2][2], wH[2][2];
    #pragma unroll
    for (int i = 0; i < 2; ++i) {
        const float4 a = uo4[i+1], n = un4[i+1];
        du[i][0] = (n.x-a.x)*INV_DT; du[i][1] = (n.y-a.y)*INV_DT;
        du[i][2] = (n.z-a.z)*INV_DT; du[i][3] = (n.w-a.w)*INV_DT;
        const float4 c = wo4[i+1], d = wn4[i+1];
        dw[i][0] = (d.x-c.x)*INV_DT; dw[i][1] = (d.y-c.y)*INV_DT;
        dw[i][2] = (d.z-c.z)*INV_DT; dw[i][3] = (d.w-c.w)*INV_DT;
        uH[i][0] = 0.5f*(uoh[i][0]+unh[i][0]); uH[i][1] = 0.5f*(uoh[i][1]+unh[i][1]);
        wH[i][0] = 0.5f*(woh[i][0]+wnh[i][0]); wH[i][1] = 0.5f*(woh[i][1]+wnh[i][1]);
    }

    float local = 0.0f;
    #pragma unroll
    for (int i = 0; i < 2; ++i) {                 // center row index (rows 1,2)
        const int ci = i + 1;
        const float uc6[6] = {uH[i][0], uA[ci][0], uA[ci][1], uA[ci][2], uA[ci][3], uH[i][1]};
        const float wc6[6] = {wH[i][0], wA[ci][0], wA[ci][1], wA[ci][2], wA[ci][3], wH[i][1]};
        const float* pcv = (i == 0) ? &p4[1].x : &p4[2].x;
        const float* pmv = (i == 0) ? &p4[0].x : &p4[1].x;
        const float pc5[5] = {pl[i], pcv[0], pcv[1], pcv[2], pcv[3]};
        const int* mkv = &mk[i].x;

        #pragma unroll
        for (int j = 0; j < 4; ++j) {
            const float u_c  = uc6[j+1], u_xm = uc6[j], u_xp = uc6[j+2];
            const float w_c  = wc6[j+1], w_xm = wc6[j], w_xp = wc6[j+2];
            const float u_ym = uA[ci-1][j], u_yp = uA[ci+1][j];
            const float w_ym = wA[ci-1][j], w_yp = wA[ci+1][j];

            // res_x (RHO = 1)
            float rx = dw[i][j]
                     + w_c * 0.5f * (w_xp - w_xm)
                     + 0.5f * ( 0.5f*(u_c + u_xm) * (w_c - w_ym)
                              + 0.5f*(u_c + u_xp) * (w_yp - w_c) )
                     + (pc5[j+1] - pc5[j])
                     - MU * (w_xm + w_xp + w_ym + w_yp - 4.0f * w_c);

            // res_y
            float ry = du[i][j]
                     + u_c * 0.5f * (u_yp - u_ym)
                     + 0.5f * ( 0.5f*(w_c + w_ym) * (u_c - u_xm)
                              + 0.5f*(w_c + w_yp) * (u_xp - u_c) )
                     + (pc5[j+1] - pmv[j])
                     - MU * (u_xm + u_xp + u_ym + u_yp - 4.0f * u_c);

            const float mf = (float)mkv[j];
            rx *= mf;
            ry *= mf;

            const int x = x0 + j;
            if (x >= 1 && x <= W - 2)
                local += rx * rx + ry * ry;
        }
    }

    // ---- block reduction ----
    #pragma unroll
    for (int o = 16; o > 0; o >>= 1)
        local += __shfl_xor_sync(0xffffffffu, local, o);

    __shared__ float s_part[8];
    __shared__ bool  s_last;
    const int lane = tid & 31, wid = tid >> 5;
    if (lane == 0) s_part[wid] = local;
    __syncthreads();
    if (tid < 32) {
        float v = (tid < 8) ? s_part[tid] : 0.0f;
        #pragma unroll
        for (int o = 4; o > 0; o >>= 1)
            v += __shfl_xor_sync(0xffffffffu, v, o);
        if (tid == 0) {
            g_part[b * TYB + blockIdx.y] = v;
            __threadfence();
            unsigned int old = atomicAdd(&g_count, 1u);
            s_last = (old == (unsigned)(NPART - 1));
        }
    }
    __syncthreads();

    // ---- last block finalizes: warp wi sums batch wi ----
    if (s_last) {
        __threadfence();
        const int wi = tid >> 5, l = tid & 31;
        double s = 0.0;
        for (int k = l; k < TYB; k += 32)
            s += (double)g_part[wi * TYB + k];
        #pragma unroll
        for (int o = 16; o > 0; o >>= 1)
            s += __shfl_xor_sync(0xffffffffu, s, o);
        if (l == 0)
            out[wi] = (float)(s * (1.0 / ((double)(H - 2) * (double)(W - 2))));
        if (tid == 0) g_count = 0;          // reset for next graph replay
    }
}

extern "C" void kernel_launch(void* const* d_in, const int* in_sizes, int n_in,
                              void* d_out, int out_size) {
    const float* v_old = (const float*)d_in[0];
    const float* v_new = (const float*)d_in[1];
    const float* p_new = (const float*)d_in[2];
    const int*   mask  = (const int*)d_in[3];
    float* out = (float*)d_out;

    dim3 grid(1, TYB, B);       // 511 x 8 = 4088 blocks, 256 threads
    ns_loss_kernel<<<grid, 256>>>(v_old, v_new, p_new, mask, out);
}